// round 1
// baseline (speedup 1.0000x reference)
#include <cuda_runtime.h>

// RoiPooling: crop_and_resize(img[0], boxes(2048), crop=7) over 512 channels.
// img: (16,28,28,512) f32  -> only image 0 used (28*28*512 = 401408 floats)
// rois: (16, 640) f32 -> 2048 boxes of 5; x1 = r[5n+3], y1 = r[5n+4]
// out:  2048*7*7*512 f32, linear order ((box*49 + py*7 + px)*512 + c)

#define IMG_H 28
#define IMG_W 28
#define IMG_C 512
#define POOLN 7
#define NBOX 2048

__global__ __launch_bounds__(128, 8) void roi_pool_kernel(
    const float4* __restrict__ img4,   // img[0] viewed as float4: (28*28, 128)
    const float*  __restrict__ rois,
    float4* __restrict__ out4)
{
    const int box = blockIdx.x;
    const int tid = threadIdx.x;   // channel-quad index 0..127

    const float x1 = rois[box * 5 + 3];
    const float y1 = rois[box * 5 + 4];
    // Match JAX numerics: window = float(4/28) added then subtracted in f32
    const float win = (float)(4.0 / 28.0);
    const float x2 = x1 + win;
    const float y2 = y1 + win;
    // (y2-y1)*(H-1)/(crop-1), f32 mul then div like JAX
    const float sx = ((x2 - x1) * 27.0f) / 6.0f;
    const float sy = ((y2 - y1) * 27.0f) / 6.0f;

    // Precompute x-direction indices/weights/mask for the 7 sample columns
    float lx[POOLN], mx[POOLN];
    int xi0[POOLN], xi1[POOLN];
#pragma unroll
    for (int j = 0; j < POOLN; j++) {
        float xs = x1 * 27.0f + (float)j * sx;
        float xf = floorf(xs);
        lx[j] = xs - xf;
        int a = (int)xf;
        xi0[j] = min(max(a, 0), IMG_W - 1);
        xi1[j] = min(max(a + 1, 0), IMG_W - 1);
        mx[j] = (xs >= 0.0f && xs <= 27.0f) ? 1.0f : 0.0f;
    }

    const int C4 = IMG_C / 4;               // 128 float4 per pixel
    float4* outp = out4 + (size_t)box * (POOLN * POOLN) * C4 + tid;

#pragma unroll
    for (int i = 0; i < POOLN; i++) {
        float ys = y1 * 27.0f + (float)i * sy;
        float yf = floorf(ys);
        float ly = ys - yf;
        int ya = (int)yf;
        int y0 = min(max(ya, 0), IMG_H - 1);
        int yb = min(max(ya + 1, 0), IMG_H - 1);
        float my = (ys >= 0.0f && ys <= 27.0f) ? 1.0f : 0.0f;
        const float4* row0 = img4 + (size_t)y0 * IMG_W * C4 + tid;
        const float4* row1 = img4 + (size_t)yb * IMG_W * C4 + tid;
        float omly = 1.0f - ly;

#pragma unroll
        for (int j = 0; j < POOLN; j++) {
            float m = my * mx[j];
            float l = lx[j];
            float4 tl = __ldg(row0 + xi0[j] * C4);
            float4 tr = __ldg(row0 + xi1[j] * C4);
            float4 bl = __ldg(row1 + xi0[j] * C4);
            float4 br = __ldg(row1 + xi1[j] * C4);
            float4 v;
            v.x = ((tl.x + (tr.x - tl.x) * l) * omly + (bl.x + (br.x - bl.x) * l) * ly) * m;
            v.y = ((tl.y + (tr.y - tl.y) * l) * omly + (bl.y + (br.y - bl.y) * l) * ly) * m;
            v.z = ((tl.z + (tr.z - tl.z) * l) * omly + (bl.z + (br.z - bl.z) * l) * ly) * m;
            v.w = ((tl.w + (tr.w - tl.w) * l) * omly + (bl.w + (br.w - bl.w) * l) * ly) * m;
            outp[(i * POOLN + j) * C4] = v;
        }
    }
}

extern "C" void kernel_launch(void* const* d_in, const int* in_sizes, int n_in,
                              void* d_out, int out_size) {
    const float* img  = (const float*)d_in[0];
    const float* rois = (const float*)d_in[1];
    float* out = (float*)d_out;
    (void)in_sizes; (void)n_in; (void)out_size;
    roi_pool_kernel<<<NBOX, 128>>>((const float4*)img, rois, (float4*)out);
}